// round 3
// baseline (speedup 1.0000x reference)
#include <cuda_runtime.h>
#include <math.h>

// ---------------- scratch (device globals; no allocations) ----------------
#define NB 16
__device__ float g_h1[NB*64*256*256];
__device__ float g_h2[NB*128*128*128];
__device__ float g_h3[NB*256*64*64];
__device__ float g_z [NB*512*32*32];
__device__ float g_zf[NB*1024*512];
__device__ float g_zq[NB*512*32*32];
__device__ float g_g1[NB*256*64*64];
__device__ float g_g2[NB*128*128*128];
__device__ float g_g3[NB*64*256*256];
__device__ float g_cn[8192];
__device__ int   g_idx[16384];

typedef unsigned long long ull;

// ---------------- f32x2 packed helpers ----------------
__device__ __forceinline__ ull fma2(ull a, ull b, ull c) {
    ull d;
    asm("fma.rn.f32x2 %0, %1, %2, %3;" : "=l"(d) : "l"(a), "l"(b), "l"(c));
    return d;
}
__device__ __forceinline__ ull splat2(float v) {
    ull d; unsigned int u = __float_as_uint(v);
    asm("mov.b64 %0, {%1, %1};" : "=l"(d) : "r"(u));
    return d;
}
__device__ __forceinline__ ull pack2(float lo, float hi) {
    ull d;
    asm("mov.b64 %0, {%1, %2};" : "=l"(d)
        : "r"(__float_as_uint(lo)), "r"(__float_as_uint(hi)));
    return d;
}
__device__ __forceinline__ void unpack2(ull v, float& lo, float& hi) {
    unsigned int a, b;
    asm("mov.b64 {%0, %1}, %2;" : "=r"(a), "=r"(b) : "l"(v));
    lo = __uint_as_float(a); hi = __uint_as_float(b);
}

// ---------------- direct 3x3 conv, pad=1, 8-wide, TC=8, FFMA2 ----------------
// Thread: 8 horizontal outputs x 8 output channels. Coalesced float4 loads,
// halo via shfl. Weights in smem [ci][tap][oc] so LDS.64 gives {w_oc,w_oc+1}.
template<int STRIDE, int ACT>
__global__ void __launch_bounds__(128) conv8_k(
    const float* __restrict__ in, const float* __restrict__ wgt,
    const float* __restrict__ bias, float* __restrict__ out,
    int Cin, int Cout, int Hin, int Win, int Hout, int Wout)
{
    constexpr int CICH = 32;
    constexpr int TC = 8, TP = 4;
    constexpr int NW = (STRIDE == 1) ? 10 : 17;   // input window per row
    __shared__ ull ws2[CICH * 9 * TP];
    float* wsf = (float*)ws2;

    const int tid  = threadIdx.x;
    const int W8   = Wout >> 3;
    const int rows = 128 / W8;
    const int q    = tid % W8;
    const int oy   = blockIdx.y * rows + tid / W8;
    const int ox0  = q * 8;
    const int ocg  = blockIdx.x * TC;
    const int n    = blockIdx.z;

    ull acc2[TP][8];
#pragma unroll
    for (int p = 0; p < TP; p++)
#pragma unroll
        for (int j = 0; j < 8; j++) acc2[p][j] = 0ull;

    bool rval[3]; int iyo[3];
#pragma unroll
    for (int ky = 0; ky < 3; ky++) {
        int iy = oy * STRIDE + ky - 1;
        rval[ky] = (iy >= 0 && iy < Hin);
        iyo[ky] = iy < 0 ? 0 : (iy >= Hin ? Hin - 1 : iy);  // clamped (loads always run)
    }

    auto loadRow = [&](float (&w)[NW], int cabs, int ky) {
        const float* rp = in + ((size_t)(n * Cin + cabs) * Hin + iyo[ky]) * Win;
        if (STRIDE == 1) {
            float4 a = *(const float4*)(rp + ox0);
            float4 b = *(const float4*)(rp + ox0 + 4);
            float lft = __shfl_up_sync(0xffffffffu, b.w, 1);
            float rgt = __shfl_down_sync(0xffffffffu, a.x, 1);
            if (q == 0) lft = 0.f;
            if (q == W8 - 1) rgt = 0.f;
            w[0]=lft; w[1]=a.x; w[2]=a.y; w[3]=a.z; w[4]=a.w;
            w[5]=b.x; w[6]=b.y; w[7]=b.z; w[8]=b.w; w[9]=rgt;
        } else {
            const int ib = ox0 * 2;
            float4 a = *(const float4*)(rp + ib);
            float4 b = *(const float4*)(rp + ib + 4);
            float4 c = *(const float4*)(rp + ib + 8);
            float4 d = *(const float4*)(rp + ib + 12);
            float lft = __shfl_up_sync(0xffffffffu, d.w, 1);
            if (q == 0) lft = 0.f;
            w[0]=lft;
            w[1]=a.x; w[2]=a.y; w[3]=a.z; w[4]=a.w;
            w[5]=b.x; w[6]=b.y; w[7]=b.z; w[8]=b.w;
            w[9]=c.x; w[10]=c.y; w[11]=c.z; w[12]=c.w;
            w[13]=d.x; w[14]=d.y; w[15]=d.z; w[16]=d.w;
        }
        if (!rval[ky]) {
#pragma unroll
            for (int i = 0; i < NW; i++) w[i] = 0.f;
        }
    };

    auto computeRow = [&](float (&w)[NW], int ci, int ky) {
        ull s[NW];
#pragma unroll
        for (int c = 0; c < NW; c++) s[c] = splat2(w[c]);
#pragma unroll
        for (int p = 0; p < TP; p++) {
#pragma unroll
            for (int kx = 0; kx < 3; kx++) {
                ull w2 = ws2[(ci * 9 + ky * 3 + kx) * TP + p];
#pragma unroll
                for (int j = 0; j < 8; j++)
                    acc2[p][j] = fma2(s[j * STRIDE + kx], w2, acc2[p][j]);
            }
        }
    };

    float bufA[NW], bufB[NW];
    for (int cc = 0; cc < Cin; cc += CICH) {
        const int chunk = min(CICH, Cin - cc);
        __syncthreads();
        for (int i = tid; i < chunk * 9 * TC; i += 128) {
            int ci = i / (9 * TC);
            int r  = i - ci * (9 * TC);
            int k  = r / TC;
            int oc = r - k * TC;
            wsf[i] = wgt[(size_t)(ocg + oc) * Cin * 9 + (size_t)(cc + ci) * 9 + k];
        }
        __syncthreads();
        const int total = chunk * 3;
        loadRow(bufA, cc, 0);
        for (int m = 0; m < total; m++) {
            const int mn = m + 1;
            if (m & 1) {
                if (mn < total) loadRow(bufA, cc + mn / 3, mn % 3);
                computeRow(bufB, m / 3, m % 3);
            } else {
                if (mn < total) loadRow(bufB, cc + mn / 3, mn % 3);
                computeRow(bufA, m / 3, m % 3);
            }
        }
    }

#pragma unroll
    for (int p = 0; p < TP; p++) {
        float b0 = bias[ocg + 2 * p];
        float b1 = bias[ocg + 2 * p + 1];
        float* o0 = out + (((size_t)n * Cout + ocg + 2 * p) * Hout + oy) * Wout + ox0;
        float* o1 = o0 + (size_t)Hout * Wout;
        float v0[8], v1[8];
#pragma unroll
        for (int j = 0; j < 8; j++) {
            float lo, hi; unpack2(acc2[p][j], lo, hi);
            float a = lo + b0, b = hi + b1;
            if (ACT == 1) { a = a > 0.f ? a : 0.f; b = b > 0.f ? b : 0.f; }
            v0[j] = a; v1[j] = b;
        }
        *(float4*)(o0)     = make_float4(v0[0], v0[1], v0[2], v0[3]);
        *(float4*)(o0 + 4) = make_float4(v0[4], v0[5], v0[6], v0[7]);
        *(float4*)(o1)     = make_float4(v1[0], v1[1], v1[2], v1[3]);
        *(float4*)(o1 + 4) = make_float4(v1[4], v1[5], v1[6], v1[7]);
    }
}

// ---------------- transposed conv k=3 s=2 p=1 op=1, 2x8 outputs, TC=8 ---------
template<int ACT>
__global__ void __launch_bounds__(128) deconv8_k(
    const float* __restrict__ in, const float* __restrict__ wgt,  // [Cin][Cout][3][3]
    const float* __restrict__ bias, float* __restrict__ out,
    int Cin, int Cout, int Hin, int Win)
{
    constexpr int CICH = 32;
    constexpr int TC = 8, TP = 4;
    __shared__ ull ws2[CICH * 9 * TP];
    float* wsf = (float*)ws2;

    const int Hout = Hin * 2, Wout = Win * 2;
    const int tid  = threadIdx.x;
    const int W8   = Wout >> 3;           // = Win/4
    const int rows = 128 / W8;            // input rows per block
    const int q    = tid % W8;
    const int a    = blockIdx.y * rows + tid / W8;  // input row
    const int b    = q * 4;                          // input col base
    const int ocg  = blockIdx.x * TC;
    const int n    = blockIdx.z;

    const bool v_a1 = (a + 1) < Hin;
    const bool v_b4 = (b + 4) < Win;
    const int  a1c  = v_a1 ? (a + 1) : a;  // clamped row for unconditional loads

    ull acc2[TP][16];   // [p][r*8 + o] : r in {0,1} out rows (2a, 2a+1), o 0..7
#pragma unroll
    for (int p = 0; p < TP; p++)
#pragma unroll
        for (int j = 0; j < 16; j++) acc2[p][j] = 0ull;

    auto loadRaw = [&](float (&w)[10], int cabs) {
        const float* ip = in + (size_t)(n * Cin + cabs) * Hin * Win;
        const float* r0 = ip + (size_t)a * Win + b;
        const float* r1 = ip + (size_t)a1c * Win + b;
        float4 v0 = *(const float4*)r0;
        float4 v1 = *(const float4*)r1;
        float e0 = __shfl_down_sync(0xffffffffu, v0.x, 1);
        float e1 = __shfl_down_sync(0xffffffffu, v1.x, 1);
        if (!v_b4) { e0 = 0.f; e1 = 0.f; }
        w[0]=v0.x; w[1]=v0.y; w[2]=v0.z; w[3]=v0.w; w[4]=e0;
        if (v_a1) { w[5]=v1.x; w[6]=v1.y; w[7]=v1.z; w[8]=v1.w; w[9]=e1; }
        else      { w[5]=0.f; w[6]=0.f; w[7]=0.f; w[8]=0.f; w[9]=0.f; }
    };

    auto computeCi = [&](float (&w)[10], int ci) {
        ull s[10];
#pragma unroll
        for (int c = 0; c < 10; c++) s[c] = splat2(w[c]);
        const ull* wp = ws2 + (size_t)ci * 9 * TP;
#pragma unroll
        for (int p = 0; p < TP; p++) {
            ull w00 = wp[0*TP+p], w01 = wp[1*TP+p], w02 = wp[2*TP+p];
            ull w10 = wp[3*TP+p], w11 = wp[4*TP+p], w12 = wp[5*TP+p];
            ull w20 = wp[6*TP+p], w21 = wp[7*TP+p], w22 = wp[8*TP+p];
#pragma unroll
            for (int qq = 0; qq < 4; qq++) {
                ull j00 = s[qq], j01 = s[qq+1], j10 = s[5+qq], j11 = s[5+qq+1];
                acc2[p][qq*2]     = fma2(j00, w11, acc2[p][qq*2]);
                acc2[p][qq*2+1]   = fma2(j00, w12, fma2(j01, w10, acc2[p][qq*2+1]));
                acc2[p][8+qq*2]   = fma2(j00, w21, fma2(j10, w01, acc2[p][8+qq*2]));
                acc2[p][8+qq*2+1] = fma2(j00, w22, fma2(j01, w20,
                                    fma2(j10, w02, fma2(j11, w00, acc2[p][8+qq*2+1]))));
            }
        }
    };

    float rawA[10], rawB[10];
    for (int cc = 0; cc < Cin; cc += CICH) {
        const int chunk = min(CICH, Cin - cc);
        __syncthreads();
        for (int i = tid; i < chunk * 9 * TC; i += 128) {
            int ci = i / (9 * TC);
            int r  = i - ci * (9 * TC);
            int k  = r / TC;
            int oc = r - k * TC;
            wsf[i] = wgt[(size_t)(cc + ci) * Cout * 9 + (size_t)(ocg + oc) * 9 + k];
        }
        __syncthreads();
        loadRaw(rawA, cc);
        for (int ci = 0; ci < chunk; ci += 2) {
            if (ci + 1 < chunk) loadRaw(rawB, cc + ci + 1);
            computeCi(rawA, ci);
            if (ci + 2 < chunk) loadRaw(rawA, cc + ci + 2);
            if (ci + 1 < chunk) computeCi(rawB, ci + 1);
        }
    }

#pragma unroll
    for (int p = 0; p < TP; p++) {
        float b0 = bias[ocg + 2 * p];
        float b1 = bias[ocg + 2 * p + 1];
        float* o0 = out + (((size_t)n * Cout + ocg + 2 * p) * Hout + 2 * a) * Wout + 8 * q;
        float* o1 = o0 + (size_t)Hout * Wout;
#pragma unroll
        for (int r = 0; r < 2; r++) {
            float v0[8], v1[8];
#pragma unroll
            for (int o = 0; o < 8; o++) {
                float lo, hi; unpack2(acc2[p][r*8 + o], lo, hi);
                float x0 = lo + b0, x1 = hi + b1;
                if (ACT == 1) { x0 = x0 > 0.f ? x0 : 0.f; x1 = x1 > 0.f ? x1 : 0.f; }
                v0[o] = x0; v1[o] = x1;
            }
            float* p0 = o0 + (size_t)r * Wout;
            float* p1 = o1 + (size_t)r * Wout;
            *(float4*)(p0)     = make_float4(v0[0], v0[1], v0[2], v0[3]);
            *(float4*)(p0 + 4) = make_float4(v0[4], v0[5], v0[6], v0[7]);
            *(float4*)(p1)     = make_float4(v1[0], v1[1], v1[2], v1[3]);
            *(float4*)(p1 + 4) = make_float4(v1[4], v1[5], v1[6], v1[7]);
        }
    }
}

// ---------------- scalar conv (final 3-channel sigmoid layer) -------------
template<int STRIDE, int TC, int ACT>
__global__ void __launch_bounds__(128) convS_k(
    const float* __restrict__ in, const float* __restrict__ wgt,
    const float* __restrict__ bias, float* __restrict__ out,
    int Cin, int Cout, int Hin, int Win, int Hout, int Wout)
{
    constexpr int CICH = 32;
    constexpr int NC = (STRIDE == 1) ? 6 : 9;
    __shared__ float ws[CICH * TC * 9];

    const int tid  = threadIdx.x;
    const int W4   = Wout >> 2;
    const int rows = 128 / W4;
    const int lane = tid % W4;
    const int row  = tid / W4;
    const int oy   = blockIdx.y * rows + row;
    const int ox0  = lane * 4;
    const int ocg  = blockIdx.x * TC;
    const int n    = blockIdx.z;

    float acc[TC][4];
#pragma unroll
    for (int a = 0; a < TC; a++)
#pragma unroll
        for (int j = 0; j < 4; j++) acc[a][j] = 0.f;

    bool cval[NC];
#pragma unroll
    for (int c = 0; c < NC; c++) {
        int ix = ox0 * STRIDE + c - 1;
        cval[c] = (ix >= 0 && ix < Win);
    }
    const int ixbase = ox0 * STRIDE - 1;
    bool rval[3]; int iyo[3];
#pragma unroll
    for (int ky = 0; ky < 3; ky++) {
        int iy = oy * STRIDE + ky - 1;
        rval[ky] = (iy >= 0 && iy < Hin);
        iyo[ky] = iy;
    }

    for (int cc = 0; cc < Cin; cc += CICH) {
        const int chunk = min(CICH, Cin - cc);
        __syncthreads();
        for (int i = tid; i < chunk * TC * 9; i += 128) {
            int ci = i / (TC * 9);
            int r  = i - ci * (TC * 9);
            int oc = r / 9;
            int k  = r - oc * 9;
            ws[i] = wgt[(size_t)(ocg + oc) * Cin * 9 + (size_t)(cc + ci) * 9 + k];
        }
        __syncthreads();
        for (int ci = 0; ci < chunk; ci++) {
            const float* ip = in + ((size_t)n * Cin + cc + ci) * Hin * Win;
            float iv[3][NC];
#pragma unroll
            for (int ky = 0; ky < 3; ky++) {
                const float* rp = ip + (long)iyo[ky] * Win + ixbase;
#pragma unroll
                for (int c = 0; c < NC; c++)
                    iv[ky][c] = (rval[ky] && cval[c]) ? rp[c] : 0.f;
            }
            const float* wp = ws + ci * TC * 9;
#pragma unroll
            for (int oc = 0; oc < TC; oc++) {
#pragma unroll
                for (int ky = 0; ky < 3; ky++)
#pragma unroll
                    for (int kx = 0; kx < 3; kx++) {
                        float wv = wp[oc * 9 + ky * 3 + kx];
#pragma unroll
                        for (int j = 0; j < 4; j++)
                            acc[oc][j] = fmaf(iv[ky][j * STRIDE + kx], wv, acc[oc][j]);
                    }
            }
        }
    }
#pragma unroll
    for (int oc = 0; oc < TC; oc++) {
        float bv = bias[ocg + oc];
        float* op = out + (((size_t)n * Cout + ocg + oc) * Hout + oy) * Wout + ox0;
#pragma unroll
        for (int j = 0; j < 4; j++) {
            float v = acc[oc][j] + bv;
            if (ACT == 1) v = v > 0.f ? v : 0.f;
            if (ACT == 2) v = 1.f / (1.f + expf(-v));
            op[j] = v;
        }
    }
}

// ---------------- z [B,512,32,32] -> zf [16384, 512] ----------------
__global__ void __launch_bounds__(256) zt_k(const float* __restrict__ z,
                                            float* __restrict__ zf)
{
    __shared__ float t[128 * 33];
    const int blk = blockIdx.x;
    const int bb  = blk >> 5;
    const int y   = blk & 31;
    const int tid = threadIdx.x;
    for (int cc = 0; cc < 512; cc += 128) {
        __syncthreads();
        for (int i = tid; i < 128 * 32; i += 256) {
            int c = i >> 5, x = i & 31;
            t[c * 33 + x] = z[(((size_t)bb * 512 + cc + c) * 32 + y) * 32 + x];
        }
        __syncthreads();
        for (int i = tid; i < 32 * 128; i += 256) {
            int x = i >> 7, c = i & 127;
            zf[((size_t)bb * 1024 + y * 32 + x) * 512 + cc + c] = t[c * 33 + x];
        }
    }
}

// ---------------- codebook row norms ----------------
__global__ void __launch_bounds__(256) cnorm_k(const float* __restrict__ cb,
                                               float* __restrict__ cn)
{
    const int warp = threadIdx.x >> 5, lane = threadIdx.x & 31;
    const int code = blockIdx.x * 8 + warp;
    const float* p = cb + (size_t)code * 512;
    float s = 0.f;
    for (int d = lane; d < 512; d += 32) { float v = p[d]; s = fmaf(v, v, s); }
#pragma unroll
    for (int o = 16; o > 0; o >>= 1) s += __shfl_xor_sync(0xffffffffu, s, o);
    if (lane == 0) cn[code] = s;
}

// ---------------- quantizer: 32 rows/block, 16 rows x 8 codes per thread -------
// smem: zs2 = 32x512 {z,z} pairs (128KB); cbs = transposed 16d x 1024c (+pad) 66KB
__global__ void __launch_bounds__(256) quant_k(const float* __restrict__ zf,
                                               const float* __restrict__ cb,
                                               const float* __restrict__ cn,
                                               int* __restrict__ idx)
{
    extern __shared__ ull smq[];
    ull*   zs2 = smq;                      // 16384 ull
    float* cbs = (float*)(smq + 16384);    // 16 * 1032 floats
    const int tid = threadIdx.x;
    const int t   = tid & 127;             // code lane
    const int rg  = tid >> 7;              // row group (0/1)
    const int r0  = blockIdx.x * 32;

    for (int i = tid; i < 32 * 512; i += 256)
        zs2[i] = splat2(zf[(size_t)r0 * 512 + i]);

    float best[16]; int bi[16];
#pragma unroll
    for (int r = 0; r < 16; r++) { best[r] = 3.4e38f; bi[r] = 0; }

    for (int ct = 0; ct < 8; ct++) {
        const int cbase = ct * 1024;
        ull dot[16][4];
#pragma unroll
        for (int r = 0; r < 16; r++)
#pragma unroll
            for (int p = 0; p < 4; p++) dot[r][p] = 0ull;

        for (int dt = 0; dt < 32; dt++) {
            const int dch = dt * 16;
            __syncthreads();
            for (int i = tid; i < 4096; i += 256) {
                int c = i >> 2, dq = i & 3;
                const float4 v = *(const float4*)(cb + (size_t)(cbase + c) * 512 + dch + dq * 4);
                float* p0 = cbs + (dq * 4) * 1032 + c;
                p0[0] = v.x; p0[1032] = v.y; p0[2064] = v.z; p0[3096] = v.w;
            }
            __syncthreads();
#pragma unroll 4
            for (int d = 0; d < 16; d++) {
                const float* crow = cbs + d * 1032 + t;
                ull c01 = pack2(crow[0],   crow[128]);
                ull c23 = pack2(crow[256], crow[384]);
                ull c45 = pack2(crow[512], crow[640]);
                ull c67 = pack2(crow[768], crow[896]);
                const ull* zp = zs2 + (size_t)rg * 16 * 512 + dch + d;
#pragma unroll
                for (int r = 0; r < 16; r++) {
                    ull zv = zp[(size_t)r * 512];
                    dot[r][0] = fma2(zv, c01, dot[r][0]);
                    dot[r][1] = fma2(zv, c23, dot[r][1]);
                    dot[r][2] = fma2(zv, c45, dot[r][2]);
                    dot[r][3] = fma2(zv, c67, dot[r][3]);
                }
            }
        }
        // candidate indices (ascending): p=0:{t,128+t}, p=1:{256+t,384+t}, ...
#pragma unroll
        for (int p = 0; p < 4; p++) {
            float n0 = cn[cbase + 256 * p + t];
            float n1 = cn[cbase + 256 * p + 128 + t];
#pragma unroll
            for (int r = 0; r < 16; r++) {
                float lo, hi; unpack2(dot[r][p], lo, hi);
                float s0 = n0 - 2.f * lo;
                float s1 = n1 - 2.f * hi;
                if (s0 < best[r]) { best[r] = s0; bi[r] = cbase + 256 * p + t; }
                if (s1 < best[r]) { best[r] = s1; bi[r] = cbase + 256 * p + 128 + t; }
            }
        }
    }
    // reduction: two independent halves (rg 0 -> rows r0..r0+15, rg 1 -> +16)
    float* sv = (float*)smq;
    int*   si = (int*)(sv + 256);
    for (int r = 0; r < 16; r++) {
        __syncthreads();
        sv[tid] = best[r]; si[tid] = bi[r];
        __syncthreads();
        for (int s = 64; s > 0; s >>= 1) {
            if ((tid & 127) < s) {
                float ov = sv[tid + s]; int oi = si[tid + s];
                if (ov < sv[tid] || (ov == sv[tid] && oi < si[tid])) { sv[tid] = ov; si[tid] = oi; }
            }
            __syncthreads();
        }
        if (t == 0) idx[r0 + rg * 16 + r] = si[tid];
    }
}

// ---------------- zq gather ----------------
__global__ void __launch_bounds__(256) zqg_k(const float* __restrict__ cb,
                                             const int* __restrict__ idx,
                                             float* __restrict__ zq)
{
    size_t i = (size_t)blockIdx.x * 256 + threadIdx.x;
    if (i >= (size_t)NB * 512 * 32 * 32) return;
    int x = (int)(i & 31);
    int y = (int)((i >> 5) & 31);
    int c = (int)((i >> 10) & 511);
    int bb = (int)(i >> 19);
    int n = bb * 1024 + y * 32 + x;
    zq[i] = cb[(size_t)idx[n] * 512 + c];
}

// ---------------- indices -> tail of output ----------------
__global__ void __launch_bounds__(256) idxout_k(const int* __restrict__ idx,
                                                float* __restrict__ out,
                                                long out_off, long out_size)
{
    int i = blockIdx.x * 256 + threadIdx.x;
    if (i < 16384 && out_off + i < out_size) out[out_off + i] = (float)idx[i];
}

// ---------------- host launcher ----------------
extern "C" void kernel_launch(void* const* d_in, const int* in_sizes, int n_in,
                              void* d_out, int out_size)
{
    const float* x  = (const float*)d_in[0];
    const float* w1 = (const float*)d_in[1];  const float* b1 = (const float*)d_in[2];
    const float* w2 = (const float*)d_in[3];  const float* b2 = (const float*)d_in[4];
    const float* w3 = (const float*)d_in[5];  const float* b3 = (const float*)d_in[6];
    const float* w4 = (const float*)d_in[7];  const float* b4 = (const float*)d_in[8];
    const float* cb = (const float*)d_in[9];
    const float* d1w = (const float*)d_in[10]; const float* d1b = (const float*)d_in[11];
    const float* d2w = (const float*)d_in[12]; const float* d2b = (const float*)d_in[13];
    const float* d3w = (const float*)d_in[14]; const float* d3b = (const float*)d_in[15];
    const float* wo = (const float*)d_in[16]; const float* bo = (const float*)d_in[17];
    float* out = (float*)d_out;

    float *h1, *h2, *h3, *z, *zf, *zq, *g1, *g2, *g3, *cn;
    int* idx;
    cudaGetSymbolAddress((void**)&h1, g_h1);
    cudaGetSymbolAddress((void**)&h2, g_h2);
    cudaGetSymbolAddress((void**)&h3, g_h3);
    cudaGetSymbolAddress((void**)&z,  g_z);
    cudaGetSymbolAddress((void**)&zf, g_zf);
    cudaGetSymbolAddress((void**)&zq, g_zq);
    cudaGetSymbolAddress((void**)&g1, g_g1);
    cudaGetSymbolAddress((void**)&g2, g_g2);
    cudaGetSymbolAddress((void**)&g3, g_g3);
    cudaGetSymbolAddress((void**)&cn, g_cn);
    cudaGetSymbolAddress((void**)&idx, g_idx);

    // Encoder (8-wide, TC=8)
    conv8_k<1, 1><<<dim3( 8, 64, NB), 128>>>(x,  w1, b1, h1,   3,  64, 256, 256, 256, 256);
    conv8_k<2, 1><<<dim3(16, 16, NB), 128>>>(h1, w2, b2, h2,  64, 128, 256, 256, 128, 128);
    conv8_k<2, 1><<<dim3(32,  4, NB), 128>>>(h2, w3, b3, h3, 128, 256, 128, 128,  64,  64);
    conv8_k<2, 0><<<dim3(64,  1, NB), 128>>>(h3, w4, b4, z,  256, 512,  64,  64,  32,  32);

    // Quantize
    zt_k<<<512, 256>>>(z, zf);
    cnorm_k<<<1024, 256>>>(cb, cn);
    cudaFuncSetAttribute(quant_k, cudaFuncAttributeMaxDynamicSharedMemorySize, 197120);
    quant_k<<<512, 256, 197120>>>(zf, cb, cn, idx);
    zqg_k<<<(NB * 512 * 32 * 32 + 255) / 256, 256>>>(cb, idx, zq);

    // Decoder (2x8-wide, TC=8)
    deconv8_k<1><<<dim3(32,  2, NB), 128>>>(zq, d1w, d1b, g1, 512, 256,  32,  32);
    deconv8_k<1><<<dim3(16,  8, NB), 128>>>(g1, d2w, d2b, g2, 256, 128,  64,  64);
    deconv8_k<1><<<dim3( 8, 32, NB), 128>>>(g2, d3w, d3b, g3, 128,  64, 128, 128);
    convS_k<1, 3, 2><<<dim3(1, 128, NB), 128>>>(g3, wo, bo, out, 64, 3, 256, 256, 256, 256);

    // Indices appended after reconstruction
    idxout_k<<<64, 256>>>(idx, out, (long)NB * 3 * 256 * 256, (long)out_size);
}

// round 4
// speedup vs baseline: 1.6958x; 1.6958x over previous
#include <cuda_runtime.h>
#include <math.h>

// ---------------- scratch (device globals; no allocations) ----------------
#define NB 16
__device__ float g_h1[NB*64*256*256];
__device__ float g_h2[NB*128*128*128];
__device__ float g_h3[NB*256*64*64];
__device__ float g_z [NB*512*32*32];
__device__ float g_zf[NB*1024*512];
__device__ float g_zq[NB*512*32*32];
__device__ float g_g1[NB*256*64*64];
__device__ float g_g2[NB*128*128*128];
__device__ float g_g3[NB*64*256*256];
__device__ float g_cn[8192];
__device__ int   g_idx[16384];

// ---------------- direct 3x3 conv, pad=1, 8-wide, TC=8, scalar ----------------
// Thread: 8 horizontal outputs x 8 output channels. Coalesced float4 loads,
// halo via shfl. Weights smem [ci][oc][ky][4] -> one LDS.128 per (oc,row).
template<int STRIDE, int ACT>
__global__ void __launch_bounds__(128) conv8s_k(
    const float* __restrict__ in, const float* __restrict__ wgt,
    const float* __restrict__ bias, float* __restrict__ out,
    int Cin, int Cout, int Hin, int Win, int Hout, int Wout)
{
    constexpr int CICH = 32;
    constexpr int TC = 8;
    constexpr int NW = (STRIDE == 1) ? 10 : 17;   // input window per row
    __shared__ float wsf[CICH * TC * 12];          // 12KB

    const int tid  = threadIdx.x;
    const int W8   = Wout >> 3;
    const int rows = 128 / W8;
    const int q    = tid % W8;
    const int oy   = blockIdx.y * rows + tid / W8;
    const int ox0  = q * 8;
    const int ocg  = blockIdx.x * TC;
    const int n    = blockIdx.z;

    float acc[TC][8];
#pragma unroll
    for (int o = 0; o < TC; o++)
#pragma unroll
        for (int j = 0; j < 8; j++) acc[o][j] = 0.f;

    bool rval[3]; int iyo[3];
#pragma unroll
    for (int ky = 0; ky < 3; ky++) {
        int iy = oy * STRIDE + ky - 1;
        rval[ky] = (iy >= 0 && iy < Hin);
        iyo[ky] = iy < 0 ? 0 : (iy >= Hin ? Hin - 1 : iy);  // clamped
    }

    auto loadRow = [&](float (&w)[NW], int cabs, int ky) {
        const float* rp = in + ((size_t)(n * Cin + cabs) * Hin + iyo[ky]) * Win;
        if (STRIDE == 1) {
            float4 a = *(const float4*)(rp + ox0);
            float4 b = *(const float4*)(rp + ox0 + 4);
            float lft = __shfl_up_sync(0xffffffffu, b.w, 1);
            float rgt = __shfl_down_sync(0xffffffffu, a.x, 1);
            if (q == 0) lft = 0.f;
            if (q == W8 - 1) rgt = 0.f;
            w[0]=lft; w[1]=a.x; w[2]=a.y; w[3]=a.z; w[4]=a.w;
            w[5]=b.x; w[6]=b.y; w[7]=b.z; w[8]=b.w; w[9]=rgt;
        } else {
            const int ib = ox0 * 2;
            float4 a = *(const float4*)(rp + ib);
            float4 b = *(const float4*)(rp + ib + 4);
            float4 c = *(const float4*)(rp + ib + 8);
            float4 d = *(const float4*)(rp + ib + 12);
            float lft = __shfl_up_sync(0xffffffffu, d.w, 1);
            if (q == 0) lft = 0.f;
            w[0]=lft;
            w[1]=a.x; w[2]=a.y; w[3]=a.z; w[4]=a.w;
            w[5]=b.x; w[6]=b.y; w[7]=b.z; w[8]=b.w;
            w[9]=c.x; w[10]=c.y; w[11]=c.z; w[12]=c.w;
            w[13]=d.x; w[14]=d.y; w[15]=d.z; w[16]=d.w;
        }
        if (!rval[ky]) {
#pragma unroll
            for (int i = 0; i < NW; i++) w[i] = 0.f;
        }
    };

    auto computeRow = [&](float (&w)[NW], int ci, int ky) {
#pragma unroll
        for (int oc = 0; oc < TC; oc++) {
            const float4 wv = *(const float4*)(wsf + (ci * TC + oc) * 12 + ky * 4);
#pragma unroll
            for (int j = 0; j < 8; j++) {
                float a = acc[oc][j];
                a = fmaf(w[j * STRIDE + 0], wv.x, a);
                a = fmaf(w[j * STRIDE + 1], wv.y, a);
                a = fmaf(w[j * STRIDE + 2], wv.z, a);
                acc[oc][j] = a;
            }
        }
    };

    float bufA[NW], bufB[NW];
    for (int cc = 0; cc < Cin; cc += CICH) {
        const int chunk = min(CICH, Cin - cc);
        __syncthreads();
        for (int i = tid; i < chunk * TC * 9; i += 128) {
            int ci = i / (TC * 9);
            int r  = i - ci * (TC * 9);
            int oc = r / 9;
            int k  = r - oc * 9;
            wsf[(ci * TC + oc) * 12 + (k / 3) * 4 + (k % 3)] =
                wgt[(size_t)(ocg + oc) * Cin * 9 + (size_t)(cc + ci) * 9 + k];
        }
        __syncthreads();
        const int total = chunk * 3;
        loadRow(bufA, cc, 0);
        for (int m = 0; m < total; m++) {
            const int mn = m + 1;
            if (m & 1) {
                if (mn < total) loadRow(bufA, cc + mn / 3, mn % 3);
                computeRow(bufB, m / 3, m % 3);
            } else {
                if (mn < total) loadRow(bufB, cc + mn / 3, mn % 3);
                computeRow(bufA, m / 3, m % 3);
            }
        }
    }

#pragma unroll
    for (int oc = 0; oc < TC; oc++) {
        float bv = bias[ocg + oc];
        float* op = out + (((size_t)n * Cout + ocg + oc) * Hout + oy) * Wout + ox0;
        float v[8];
#pragma unroll
        for (int j = 0; j < 8; j++) {
            float a = acc[oc][j] + bv;
            if (ACT == 1) a = a > 0.f ? a : 0.f;
            v[j] = a;
        }
        *(float4*)(op)     = make_float4(v[0], v[1], v[2], v[3]);
        *(float4*)(op + 4) = make_float4(v[4], v[5], v[6], v[7]);
    }
}

// ---------------- transposed conv k=3 s=2 p=1 op=1, scalar, TC=8 --------------
// R1 structure (proven): thread = 2x4 output block for 8 ocs; weights [ci][oc][12].
template<int ACT>
__global__ void __launch_bounds__(128) deconvS_k(
    const float* __restrict__ in, const float* __restrict__ wgt,  // [Cin][Cout][3][3]
    const float* __restrict__ bias, float* __restrict__ out,
    int Cin, int Cout, int Hin, int Win)
{
    constexpr int CICH = 32;
    constexpr int TC = 8;
    __shared__ float wsf[CICH * TC * 12];  // 12KB

    const int Hout = Hin * 2, Wout = Win * 2;
    const int tid  = threadIdx.x;
    const int W4   = Wout >> 2;
    const int rows = 128 / W4;
    const int q    = tid % W4;
    const int a    = blockIdx.y * rows + tid / W4;  // input row
    const int b    = q * 2;                          // input col base
    const int ocg  = blockIdx.x * TC;
    const int n    = blockIdx.z;

    const bool v_a1 = (a + 1) < Hin;
    const bool v_b2 = (b + 2) < Win;

    float acc[TC][8];
#pragma unroll
    for (int o = 0; o < TC; o++)
#pragma unroll
        for (int j = 0; j < 8; j++) acc[o][j] = 0.f;

    auto loadRaw = [&](float (&rw)[6], int cabs) {
        const float* ip = in + ((size_t)n * Cin + cabs) * Hin * Win;
        const float* r0 = ip + (size_t)a * Win + b;
        rw[0] = r0[0];
        rw[1] = r0[1];
        rw[2] = v_b2 ? r0[2] : 0.f;
        if (v_a1) {
            const float* r1 = r0 + Win;
            rw[3] = r1[0]; rw[4] = r1[1]; rw[5] = v_b2 ? r1[2] : 0.f;
        } else {
            rw[3] = 0.f; rw[4] = 0.f; rw[5] = 0.f;
        }
    };
    auto computeCi = [&](float (&rw)[6], int ci) {
        float i00 = rw[0], i01 = rw[1], i02 = rw[2];
        float i10 = rw[3], i11 = rw[4], i12 = rw[5];
#pragma unroll
        for (int oc = 0; oc < TC; oc++) {
            const float* wp = wsf + (ci * TC + oc) * 12;
            const float4 A = *(const float4*)(wp);       // w00 w01 w02 w10
            const float4 B = *(const float4*)(wp + 4);   // w11 w12 w20 w21
            const float w22 = wp[8];
            float w00=A.x, w01=A.y, w02=A.z, w10=A.w;
            float w11=B.x, w12=B.y, w20=B.z, w21=B.w;
            acc[oc][0] = fmaf(i00, w11, acc[oc][0]);
            acc[oc][1] = fmaf(i00, w12, fmaf(i01, w10, acc[oc][1]));
            acc[oc][2] = fmaf(i01, w11, acc[oc][2]);
            acc[oc][3] = fmaf(i01, w12, fmaf(i02, w10, acc[oc][3]));
            acc[oc][4] = fmaf(i00, w21, fmaf(i10, w01, acc[oc][4]));
            acc[oc][5] = fmaf(i00, w22, fmaf(i01, w20, fmaf(i10, w02, fmaf(i11, w00, acc[oc][5]))));
            acc[oc][6] = fmaf(i01, w21, fmaf(i11, w01, acc[oc][6]));
            acc[oc][7] = fmaf(i01, w22, fmaf(i02, w20, fmaf(i11, w02, fmaf(i12, w00, acc[oc][7]))));
        }
    };

    float rawA[6], rawB[6];
    for (int cc = 0; cc < Cin; cc += CICH) {
        const int chunk = min(CICH, Cin - cc);
        __syncthreads();
        for (int i = tid; i < chunk * TC * 9; i += 128) {
            int ci = i / (TC * 9);
            int r  = i - ci * (TC * 9);
            int oc = r / 9;
            int k  = r - oc * 9;
            wsf[(ci * TC + oc) * 12 + k] =
                wgt[(size_t)(cc + ci) * Cout * 9 + (size_t)(ocg + oc) * 9 + k];
        }
        __syncthreads();
        loadRaw(rawA, cc);
        for (int ci = 0; ci < chunk; ci += 2) {
            if (ci + 1 < chunk) loadRaw(rawB, cc + ci + 1);
            computeCi(rawA, ci);
            if (ci + 2 < chunk) loadRaw(rawA, cc + ci + 2);
            if (ci + 1 < chunk) computeCi(rawB, ci + 1);
        }
    }

#pragma unroll
    for (int oc = 0; oc < TC; oc++) {
        float bv = bias[ocg + oc];
        float* op = out + (((size_t)n * Cout + ocg + oc) * Hout + 2 * a) * Wout + 4 * q;
        float v0[4], v1[4];
#pragma unroll
        for (int j = 0; j < 4; j++) {
            float x0 = acc[oc][j] + bv;
            float x1 = acc[oc][4 + j] + bv;
            if (ACT == 1) { x0 = x0 > 0.f ? x0 : 0.f; x1 = x1 > 0.f ? x1 : 0.f; }
            v0[j] = x0; v1[j] = x1;
        }
        *(float4*)(op)        = make_float4(v0[0], v0[1], v0[2], v0[3]);
        *(float4*)(op + Wout) = make_float4(v1[0], v1[1], v1[2], v1[3]);
    }
}

// ---------------- scalar conv (final 3-channel sigmoid layer) -------------
template<int STRIDE, int TC, int ACT>
__global__ void __launch_bounds__(128) convS_k(
    const float* __restrict__ in, const float* __restrict__ wgt,
    const float* __restrict__ bias, float* __restrict__ out,
    int Cin, int Cout, int Hin, int Win, int Hout, int Wout)
{
    constexpr int CICH = 32;
    constexpr int NC = (STRIDE == 1) ? 6 : 9;
    __shared__ float ws[CICH * TC * 9];

    const int tid  = threadIdx.x;
    const int W4   = Wout >> 2;
    const int rows = 128 / W4;
    const int lane = tid % W4;
    const int row  = tid / W4;
    const int oy   = blockIdx.y * rows + row;
    const int ox0  = lane * 4;
    const int ocg  = blockIdx.x * TC;
    const int n    = blockIdx.z;

    float acc[TC][4];
#pragma unroll
    for (int a = 0; a < TC; a++)
#pragma unroll
        for (int j = 0; j < 4; j++) acc[a][j] = 0.f;

    bool cval[NC];
#pragma unroll
    for (int c = 0; c < NC; c++) {
        int ix = ox0 * STRIDE + c - 1;
        cval[c] = (ix >= 0 && ix < Win);
    }
    const int ixbase = ox0 * STRIDE - 1;
    bool rval[3]; int iyo[3];
#pragma unroll
    for (int ky = 0; ky < 3; ky++) {
        int iy = oy * STRIDE + ky - 1;
        rval[ky] = (iy >= 0 && iy < Hin);
        iyo[ky] = iy;
    }

    for (int cc = 0; cc < Cin; cc += CICH) {
        const int chunk = min(CICH, Cin - cc);
        __syncthreads();
        for (int i = tid; i < chunk * TC * 9; i += 128) {
            int ci = i / (TC * 9);
            int r  = i - ci * (TC * 9);
            int oc = r / 9;
            int k  = r - oc * 9;
            ws[i] = wgt[(size_t)(ocg + oc) * Cin * 9 + (size_t)(cc + ci) * 9 + k];
        }
        __syncthreads();
        for (int ci = 0; ci < chunk; ci++) {
            const float* ip = in + ((size_t)n * Cin + cc + ci) * Hin * Win;
            float iv[3][NC];
#pragma unroll
            for (int ky = 0; ky < 3; ky++) {
                const float* rp = ip + (long)iyo[ky] * Win + ixbase;
#pragma unroll
                for (int c = 0; c < NC; c++)
                    iv[ky][c] = (rval[ky] && cval[c]) ? rp[c] : 0.f;
            }
            const float* wp = ws + ci * TC * 9;
#pragma unroll
            for (int oc = 0; oc < TC; oc++) {
#pragma unroll
                for (int ky = 0; ky < 3; ky++)
#pragma unroll
                    for (int kx = 0; kx < 3; kx++) {
                        float wv = wp[oc * 9 + ky * 3 + kx];
#pragma unroll
                        for (int j = 0; j < 4; j++)
                            acc[oc][j] = fmaf(iv[ky][j * STRIDE + kx], wv, acc[oc][j]);
                    }
            }
        }
    }
#pragma unroll
    for (int oc = 0; oc < TC; oc++) {
        float bv = bias[ocg + oc];
        float* op = out + (((size_t)n * Cout + ocg + oc) * Hout + oy) * Wout + ox0;
#pragma unroll
        for (int j = 0; j < 4; j++) {
            float v = acc[oc][j] + bv;
            if (ACT == 1) v = v > 0.f ? v : 0.f;
            if (ACT == 2) v = 1.f / (1.f + expf(-v));
            op[j] = v;
        }
    }
}

// ---------------- z [B,512,32,32] -> zf [16384, 512] ----------------
__global__ void __launch_bounds__(256) zt_k(const float* __restrict__ z,
                                            float* __restrict__ zf)
{
    __shared__ float t[128 * 33];
    const int blk = blockIdx.x;
    const int bb  = blk >> 5;
    const int y   = blk & 31;
    const int tid = threadIdx.x;
    for (int cc = 0; cc < 512; cc += 128) {
        __syncthreads();
        for (int i = tid; i < 128 * 32; i += 256) {
            int c = i >> 5, x = i & 31;
            t[c * 33 + x] = z[(((size_t)bb * 512 + cc + c) * 32 + y) * 32 + x];
        }
        __syncthreads();
        for (int i = tid; i < 32 * 128; i += 256) {
            int x = i >> 7, c = i & 127;
            zf[((size_t)bb * 1024 + y * 32 + x) * 512 + cc + c] = t[c * 33 + x];
        }
    }
}

// ---------------- codebook row norms ----------------
__global__ void __launch_bounds__(256) cnorm_k(const float* __restrict__ cb,
                                               float* __restrict__ cn)
{
    const int warp = threadIdx.x >> 5, lane = threadIdx.x & 31;
    const int code = blockIdx.x * 8 + warp;
    const float* p = cb + (size_t)code * 512;
    float s = 0.f;
    for (int d = lane; d < 512; d += 32) { float v = p[d]; s = fmaf(v, v, s); }
#pragma unroll
    for (int o = 16; o > 0; o >>= 1) s += __shfl_xor_sync(0xffffffffu, s, o);
    if (lane == 0) cn[code] = s;
}

// ---------------- quantizer: 16 rows/block, 16 rows x 4 codes per thread -------
// smem: zs transposed [512][16] pitch 20 (40KB); cbs transposed [16][1024] pitch 1033 (66KB)
#define ZP 20
#define CP 1033
__global__ void __launch_bounds__(256) quant_k(const float* __restrict__ zf,
                                               const float* __restrict__ cb,
                                               const float* __restrict__ cn,
                                               int* __restrict__ idx)
{
    extern __shared__ float sm[];
    float* zs  = sm;              // 512*ZP
    float* cbs = sm + 512 * ZP;   // 16*CP
    const int tid = threadIdx.x;
    const int r0  = blockIdx.x * 16;

    for (int i = tid; i < 16 * 512; i += 256) {
        int r = i >> 9, d = i & 511;
        zs[d * ZP + r] = zf[(size_t)(r0 + r) * 512 + d];
    }

    float best[16]; int bi[16];
#pragma unroll
    for (int r = 0; r < 16; r++) { best[r] = 3.4e38f; bi[r] = 0; }

    for (int ct = 0; ct < 8; ct++) {
        const int cbase = ct * 1024;
        float dot[16][4];
#pragma unroll
        for (int r = 0; r < 16; r++)
#pragma unroll
            for (int p = 0; p < 4; p++) dot[r][p] = 0.f;

        for (int dch = 0; dch < 32; dch++) {
            const int dbase = dch * 16;
            __syncthreads();
            for (int i = tid; i < 4096; i += 256) {
                int c = i >> 2, dq = i & 3;
                const float4 v = *(const float4*)(cb + (size_t)(cbase + c) * 512 + dbase + dq * 4);
                float* p0 = cbs + (dq * 4) * CP + c;
                p0[0] = v.x; p0[CP] = v.y; p0[2 * CP] = v.z; p0[3 * CP] = v.w;
            }
            __syncthreads();
#pragma unroll 4
            for (int d = 0; d < 16; d++) {
                const float* zp = zs + (dbase + d) * ZP;
                const float4 za = *(const float4*)(zp);
                const float4 zb = *(const float4*)(zp + 4);
                const float4 zc = *(const float4*)(zp + 8);
                const float4 zd = *(const float4*)(zp + 12);
                const float* crow = cbs + d * CP + tid;
#pragma unroll
                for (int p = 0; p < 4; p++) {
                    float cv = crow[p * 256];
                    dot[0][p]  = fmaf(za.x, cv, dot[0][p]);
                    dot[1][p]  = fmaf(za.y, cv, dot[1][p]);
                    dot[2][p]  = fmaf(za.z, cv, dot[2][p]);
                    dot[3][p]  = fmaf(za.w, cv, dot[3][p]);
                    dot[4][p]  = fmaf(zb.x, cv, dot[4][p]);
                    dot[5][p]  = fmaf(zb.y, cv, dot[5][p]);
                    dot[6][p]  = fmaf(zb.z, cv, dot[6][p]);
                    dot[7][p]  = fmaf(zb.w, cv, dot[7][p]);
                    dot[8][p]  = fmaf(zc.x, cv, dot[8][p]);
                    dot[9][p]  = fmaf(zc.y, cv, dot[9][p]);
                    dot[10][p] = fmaf(zc.z, cv, dot[10][p]);
                    dot[11][p] = fmaf(zc.w, cv, dot[11][p]);
                    dot[12][p] = fmaf(zd.x, cv, dot[12][p]);
                    dot[13][p] = fmaf(zd.y, cv, dot[13][p]);
                    dot[14][p] = fmaf(zd.z, cv, dot[14][p]);
                    dot[15][p] = fmaf(zd.w, cv, dot[15][p]);
                }
            }
        }
#pragma unroll
        for (int p = 0; p < 4; p++) {
            const int ci = cbase + p * 256 + tid;
            float nv = cn[ci];
#pragma unroll
            for (int r = 0; r < 16; r++) {
                float s = nv - 2.f * dot[r][p];
                if (s < best[r]) { best[r] = s; bi[r] = ci; }
            }
        }
    }
    // block-wide argmin per row (lowest index on ties)
    float* sv = sm;
    int*   si = (int*)(sm + 256);
    for (int r = 0; r < 16; r++) {
        __syncthreads();
        sv[tid] = best[r]; si[tid] = bi[r];
        __syncthreads();
        for (int s = 128; s > 0; s >>= 1) {
            if (tid < s) {
                float ov = sv[tid + s]; int oi = si[tid + s];
                if (ov < sv[tid] || (ov == sv[tid] && oi < si[tid])) { sv[tid] = ov; si[tid] = oi; }
            }
            __syncthreads();
        }
        if (tid == 0) idx[r0 + r] = si[0];
    }
}

// ---------------- zq gather ----------------
__global__ void __launch_bounds__(256) zqg_k(const float* __restrict__ cb,
                                             const int* __restrict__ idx,
                                             float* __restrict__ zq)
{
    size_t i = (size_t)blockIdx.x * 256 + threadIdx.x;
    if (i >= (size_t)NB * 512 * 32 * 32) return;
    int x = (int)(i & 31);
    int y = (int)((i >> 5) & 31);
    int c = (int)((i >> 10) & 511);
    int bb = (int)(i >> 19);
    int n = bb * 1024 + y * 32 + x;
    zq[i] = cb[(size_t)idx[n] * 512 + c];
}

// ---------------- indices -> tail of output ----------------
__global__ void __launch_bounds__(256) idxout_k(const int* __restrict__ idx,
                                                float* __restrict__ out,
                                                long out_off, long out_size)
{
    int i = blockIdx.x * 256 + threadIdx.x;
    if (i < 16384 && out_off + i < out_size) out[out_off + i] = (float)idx[i];
}

// ---------------- host launcher ----------------
extern "C" void kernel_launch(void* const* d_in, const int* in_sizes, int n_in,
                              void* d_out, int out_size)
{
    const float* x  = (const float*)d_in[0];
    const float* w1 = (const float*)d_in[1];  const float* b1 = (const float*)d_in[2];
    const float* w2 = (const float*)d_in[3];  const float* b2 = (const float*)d_in[4];
    const float* w3 = (const float*)d_in[5];  const float* b3 = (const float*)d_in[6];
    const float* w4 = (const float*)d_in[7];  const float* b4 = (const float*)d_in[8];
    const float* cb = (const float*)d_in[9];
    const float* d1w = (const float*)d_in[10]; const float* d1b = (const float*)d_in[11];
    const float* d2w = (const float*)d_in[12]; const float* d2b = (const float*)d_in[13];
    const float* d3w = (const float*)d_in[14]; const float* d3b = (const float*)d_in[15];
    const float* wo = (const float*)d_in[16]; const float* bo = (const float*)d_in[17];
    float* out = (float*)d_out;

    float *h1, *h2, *h3, *z, *zf, *zq, *g1, *g2, *g3, *cn;
    int* idx;
    cudaGetSymbolAddress((void**)&h1, g_h1);
    cudaGetSymbolAddress((void**)&h2, g_h2);
    cudaGetSymbolAddress((void**)&h3, g_h3);
    cudaGetSymbolAddress((void**)&z,  g_z);
    cudaGetSymbolAddress((void**)&zf, g_zf);
    cudaGetSymbolAddress((void**)&zq, g_zq);
    cudaGetSymbolAddress((void**)&g1, g_g1);
    cudaGetSymbolAddress((void**)&g2, g_g2);
    cudaGetSymbolAddress((void**)&g3, g_g3);
    cudaGetSymbolAddress((void**)&cn, g_cn);
    cudaGetSymbolAddress((void**)&idx, g_idx);

    // Encoder (8-wide scalar, TC=8)
    conv8s_k<1, 1><<<dim3( 8, 64, NB), 128>>>(x,  w1, b1, h1,   3,  64, 256, 256, 256, 256);
    conv8s_k<2, 1><<<dim3(16, 16, NB), 128>>>(h1, w2, b2, h2,  64, 128, 256, 256, 128, 128);
    conv8s_k<2, 1><<<dim3(32,  4, NB), 128>>>(h2, w3, b3, h3, 128, 256, 128, 128,  64,  64);
    conv8s_k<2, 0><<<dim3(64,  1, NB), 128>>>(h3, w4, b4, z,  256, 512,  64,  64,  32,  32);

    // Quantize
    zt_k<<<512, 256>>>(z, zf);
    cnorm_k<<<1024, 256>>>(cb, cn);
    const int qsmem = (512 * ZP + 16 * CP) * 4;  // 40960 + 66112 = 107072 B
    cudaFuncSetAttribute(quant_k, cudaFuncAttributeMaxDynamicSharedMemorySize, qsmem);
    quant_k<<<1024, 256, qsmem>>>(zf, cb, cn, idx);
    zqg_k<<<(NB * 512 * 32 * 32 + 255) / 256, 256>>>(cb, idx, zq);

    // Decoder (scalar, TC=8)
    deconvS_k<1><<<dim3(32,  4, NB), 128>>>(zq, d1w, d1b, g1, 512, 256,  32,  32);
    deconvS_k<1><<<dim3(16, 16, NB), 128>>>(g1, d2w, d2b, g2, 256, 128,  64,  64);
    deconvS_k<1><<<dim3( 8, 64, NB), 128>>>(g2, d3w, d3b, g3, 128,  64, 128, 128);
    convS_k<1, 3, 2><<<dim3(1, 128, NB), 128>>>(g3, wo, bo, out, 64, 3, 256, 256, 256, 256);

    // Indices appended after reconstruction
    idxout_k<<<64, 256>>>(idx, out, (long)NB * 3 * 256 * 256, (long)out_size);
}